// round 4
// baseline (speedup 1.0000x reference)
#include <cuda_runtime.h>

// Problem constants
#define VDIM 5000
#define MDIM 256
#define KDIM 64
#define NCH 40      // split-K chunks over V
#define CHUNK 128   // V elements per chunk (40*128 = 5120 >= 5000, padded)
#define LMB 0.001f
#define NITER 4

// ---------------------------------------------------------------------------
// Device scratch (allocation-free rule: __device__ globals)
// ---------------------------------------------------------------------------
__device__ float g_part[2 * NCH * 4 * 64 * 64];   // split-K partials (5.24 MB)
__device__ float g_A[64 * 256];                   // A  = tx @ fx
__device__ float g_T[64 * 256];                   // T  = ty @ fy
__device__ float g_AAt[4096];                     // A A^T
__device__ float g_TA[4096];                      // T A^T
__device__ float g_S[4096];                       // sy^T sy
__device__ float g_Qm[4096];                      // inv(sx)
__device__ float g_Sinv[4096];                    // inv(S)
__device__ float g_AAti[4096];                    // inv(AAt)
__device__ float g_Rp[4096];                      // R' = S * TA  (rhs matrix)
__device__ float g_QtP[4096];                     // Q^T diag(ex) Q  (symmetric)
__device__ float g_QtQ[4096];                     // Q^T Q
__device__ float g_U1[4096];                      // AAt + LMB * P^T P
__device__ float g_L3[4096];                      // LMB * Sinv * diag(ey) * S
__device__ float g_L4[4096];                      // L3 * diag(ey)
__device__ float g_R1[4096];                      // U1  * AAti
__device__ float g_R2[4096];                      // QtP * AAti
__device__ float g_R4[4096];                      // QtQ * AAti
__device__ float g_Tmp[4096];                     // Sinv * R'
__device__ float g_X0[4096];                      // Sinv * R' * AAti (precond rhs)
__device__ float g_X[4096];                       // iterate / solution
__device__ float g_M1[4096], g_M2[4096], g_M4[4096];

// ---------------------------------------------------------------------------
// 1) Big GEMMs: A = tx[64,V] @ fx[V,256], T = ty @ fy.  Split-K, deterministic.
//    grid = (NCH, 4 col-tiles of 64, 2 matrices), block = 256
// ---------------------------------------------------------------------------
__global__ void big_gemm(const float* __restrict__ fx, const float* __restrict__ fy,
                         const float* __restrict__ tx, const float* __restrict__ ty) {
    int ch = blockIdx.x, ct = blockIdx.y, mz = blockIdx.z;
    const float* f = mz ? fy : fx;   // [V][256]
    const float* t = mz ? ty : tx;   // [64][V]

    __shared__ float ts[64][17];
    __shared__ float fs[16][64];

    int tid = threadIdx.x;
    int row = tid & 63;
    int cg  = tid >> 6;              // 4 column groups of 16

    float acc[16];
#pragma unroll
    for (int i = 0; i < 16; i++) acc[i] = 0.f;

    int k0 = ch * CHUNK;
    for (int sub = 0; sub < CHUNK / 16; ++sub) {
        int kb = k0 + sub * 16;
        // load t tile: 64 rows x 16 k
#pragma unroll
        for (int i = 0; i < 4; i++) {
            int idx = tid + i * 256;
            int r = idx >> 4, kk = idx & 15;
            int k = kb + kk;
            ts[r][kk] = (k < VDIM) ? t[r * VDIM + k] : 0.f;
        }
        // load f tile: 16 k x 64 cols
#pragma unroll
        for (int i = 0; i < 4; i++) {
            int idx = tid + i * 256;
            int kk = idx >> 6, c = idx & 63;
            int k = kb + kk;
            fs[kk][c] = (k < VDIM) ? f[k * MDIM + ct * 64 + c] : 0.f;
        }
        __syncthreads();
#pragma unroll
        for (int kk = 0; kk < 16; kk++) {
            float a = ts[row][kk];
#pragma unroll
            for (int c = 0; c < 16; c++) acc[c] += a * fs[kk][cg * 16 + c];
        }
        __syncthreads();
    }
    float* p = &g_part[((((size_t)mz * NCH + ch) * 4 + ct) * 64 + row) * 64 + cg * 16];
#pragma unroll
    for (int c = 0; c < 16; c++) p[c] = acc[c];
}

// Deterministic fixed-order reduction of split-K partials -> g_A, g_T.
// Extra blocks (128..131) also compute S = sy^T sy (independent of A/T).
__global__ void reduce_AT(const float* __restrict__ sy) {
    if (blockIdx.x >= 128) {
        int slab = blockIdx.x - 128, tid = threadIdx.x;
        for (int i = 0; i < 4; i++) {
            int o = tid + i * 256;
            int r = slab * 16 + (o >> 6), c = o & 63;
            float s = 0.f;
            for (int k = 0; k < 64; k++) s += sy[k * 64 + r] * sy[k * 64 + c];
            g_S[r * 64 + c] = s;
        }
        return;
    }
    int idx = blockIdx.x * 256 + threadIdx.x;  // 0..32767
    int mz  = idx >> 14;
    int rem = idx & 16383;
    int r   = rem >> 8;
    int c   = rem & 255;
    int ct  = c >> 6, cc = c & 63;
    float s = 0.f;
    for (int ch = 0; ch < NCH; ch++)
        s += g_part[((((size_t)mz * NCH + ch) * 4 + ct) * 64 + r) * 64 + cc];
    (mz ? g_T : g_A)[r * 256 + c] = s;
}

// ---------------------------------------------------------------------------
// 2) setup1: AAt = A A^T, TA = T A^T (K=256).  grid = 8 (2 jobs x 4 slabs)
// ---------------------------------------------------------------------------
__global__ void setup1() {
    int job = blockIdx.x >> 2, slab = blockIdx.x & 3;
    int tid = threadIdx.x;
    const float* L = job ? g_T : g_A;
    float* C = job ? g_TA : g_AAt;
    for (int i = 0; i < 4; i++) {
        int o = tid + i * 256;
        int r = slab * 16 + (o >> 6), c = o & 63;
        float s = 0.f;
        for (int k = 0; k < 256; k++) s += L[r * 256 + k] * g_A[c * 256 + k];
        C[r * 64 + c] = s;
    }
}

// ---------------------------------------------------------------------------
// Gauss-Jordan 64x64 inversion, no pivoting (inputs SPD or ~I), 1 block of 256.
// Augmented matrix is 64 x 128; each thread owns row (tid&63) and one of 4
// column groups of 32 (flat over the 128 columns).
// ---------------------------------------------------------------------------
__device__ void gj_inv(const float* __restrict__ Ain, float* __restrict__ Aout) {
    __shared__ float aug[64][129];   // 128 cols + pad
    __shared__ float pinv;
    int tid = threadIdx.x;
    int r = tid & 63, j0 = (tid >> 6) * 32;
    for (int jj = 0; jj < 32; jj++) {
        int j = j0 + jj;
        aug[r][j] = (j < 64) ? Ain[r * 64 + j] : ((r == (j - 64)) ? 1.f : 0.f);
    }
    __syncthreads();
    for (int p = 0; p < 64; p++) {
        if (tid == 0) pinv = 1.f / aug[p][p];
        __syncthreads();
        if (r == p)
            for (int jj = 0; jj < 32; jj++) aug[p][j0 + jj] *= pinv;
        __syncthreads();
        float f = aug[r][p];          // read before elimination writes
        __syncthreads();
        if (r != p)
            for (int jj = 0; jj < 32; jj++) aug[r][j0 + jj] -= f * aug[p][j0 + jj];
        __syncthreads();
    }
    for (int jj = 0; jj < 32; jj++) {
        int j = j0 + jj;
        if (j >= 64) Aout[r * 64 + (j - 64)] = aug[r][j];
    }
}

// setup2: block0 inv(sx), block1 inv(S), block2 inv(AAt), blocks3-6: R' = S*TA
__global__ void setup2(const float* __restrict__ sx) {
    int b = blockIdx.x;
    if (b == 0)      gj_inv(sx,    g_Qm);
    else if (b == 1) gj_inv(g_S,   g_Sinv);
    else if (b == 2) gj_inv(g_AAt, g_AAti);
    else {
        int slab = b - 3, tid = threadIdx.x;
        for (int i = 0; i < 4; i++) {
            int o = tid + i * 256;
            int r = slab * 16 + (o >> 6), c = o & 63;
            float s = 0.f;
            for (int k = 0; k < 64; k++) s += g_S[r * 64 + k] * g_TA[k * 64 + c];
            g_Rp[r * 64 + c] = s;
        }
    }
}

// setup3: QtP, QtQ, U1 = AAt + LMB*PtP, L3 = LMB*Sinv*diag(ey)*S.  grid=16
__global__ void setup3(const float* __restrict__ ex, const float* __restrict__ ey) {
    int job = blockIdx.x >> 2, slab = blockIdx.x & 3, tid = threadIdx.x;
    for (int i = 0; i < 4; i++) {
        int o = tid + i * 256;
        int r = slab * 16 + (o >> 6), c = o & 63;
        float s = 0.f;
        if (job == 0) {
            for (int k = 0; k < 64; k++) s += g_Qm[k * 64 + r] * ex[k] * g_Qm[k * 64 + c];
            g_QtP[r * 64 + c] = s;
        } else if (job == 1) {
            for (int k = 0; k < 64; k++) s += g_Qm[k * 64 + r] * g_Qm[k * 64 + c];
            g_QtQ[r * 64 + c] = s;
        } else if (job == 2) {
            for (int k = 0; k < 64; k++) { float e = ex[k]; s += e * e * g_Qm[k * 64 + r] * g_Qm[k * 64 + c]; }
            g_U1[r * 64 + c] = g_AAt[r * 64 + c] + LMB * s;
        } else {
            for (int k = 0; k < 64; k++) s += g_Sinv[r * 64 + k] * ey[k] * g_S[k * 64 + c];
            g_L3[r * 64 + c] = LMB * s;
        }
    }
}

// setup4: R1=U1*AAti, R2=QtP*AAti, R4=QtQ*AAti, Tmp=Sinv*R', L4=L3*diag(ey). grid=20
__global__ void setup4(const float* __restrict__ ey) {
    int job = blockIdx.x >> 2, slab = blockIdx.x & 3, tid = threadIdx.x;
    for (int i = 0; i < 4; i++) {
        int o = tid + i * 256;
        int r = slab * 16 + (o >> 6), c = o & 63;
        if (job == 4) { g_L4[r * 64 + c] = g_L3[r * 64 + c] * ey[c]; continue; }
        const float* Am; float* Cm;
        const float* Bm = (job == 3) ? g_Rp : g_AAti;
        if (job == 0)      { Am = g_U1;   Cm = g_R1; }
        else if (job == 1) { Am = g_QtP;  Cm = g_R2; }
        else if (job == 2) { Am = g_QtQ;  Cm = g_R4; }
        else               { Am = g_Sinv; Cm = g_Tmp; }
        float s = 0.f;
        for (int k = 0; k < 64; k++) s += Am[r * 64 + k] * Bm[k * 64 + c];
        Cm[r * 64 + c] = s;
    }
}

// setup5: X0 = Tmp * AAti; X = X0.  grid=4
__global__ void setup5() {
    int slab = blockIdx.x, tid = threadIdx.x;
    for (int i = 0; i < 4; i++) {
        int o = tid + i * 256;
        int r = slab * 16 + (o >> 6), c = o & 63;
        float s = 0.f;
        for (int k = 0; k < 64; k++) s += g_Tmp[r * 64 + k] * g_AAti[k * 64 + c];
        g_X0[r * 64 + c] = s;
        g_X[r * 64 + c]  = s;
    }
}

// ---------------------------------------------------------------------------
// Richardson iteration (preconditioned):
//   X <- X + X0 - X*R1 + LMB*diag(ey)*(X*R2) + L3*(X*R2) - L4*(X*R4)
// ---------------------------------------------------------------------------
__global__ void iterA() {   // M1 = X*R1, M2 = X*R2, M4 = X*R4.  grid=12
    int job = blockIdx.x >> 2, slab = blockIdx.x & 3, tid = threadIdx.x;
    const float* Bm = (job == 0) ? g_R1 : (job == 1) ? g_R2 : g_R4;
    float* Cm       = (job == 0) ? g_M1 : (job == 1) ? g_M2 : g_M4;
    for (int i = 0; i < 4; i++) {
        int o = tid + i * 256;
        int r = slab * 16 + (o >> 6), c = o & 63;
        float s = 0.f;
        for (int k = 0; k < 64; k++) s += g_X[r * 64 + k] * Bm[k * 64 + c];
        Cm[r * 64 + c] = s;
    }
}

// combine; on the final iteration also writes the output buffer. grid=4
__global__ void iterB(const float* __restrict__ ey, float* __restrict__ out) {
    int slab = blockIdx.x, tid = threadIdx.x;
    for (int i = 0; i < 4; i++) {
        int o = tid + i * 256;
        int r = slab * 16 + (o >> 6), c = o & 63;
        float s = g_X[r * 64 + c] + g_X0[r * 64 + c] - g_M1[r * 64 + c]
                + LMB * ey[r] * g_M2[r * 64 + c];
        for (int k = 0; k < 64; k++)
            s += g_L3[r * 64 + k] * g_M2[k * 64 + c] - g_L4[r * 64 + k] * g_M4[k * 64 + c];
        g_X[r * 64 + c] = s;
        if (out) out[r * 64 + c] = s;
    }
}

// ---------------------------------------------------------------------------
// Launch: graph-capturable, allocation-free, deterministic.
// ---------------------------------------------------------------------------
extern "C" void kernel_launch(void* const* d_in, const int* in_sizes, int n_in,
                              void* d_out, int out_size) {
    // Map inputs by element count; pairs keep x-then-y order.
    const float *fx = nullptr, *fy = nullptr, *ex = nullptr, *ey = nullptr;
    const float *tx = nullptr, *ty = nullptr, *sx = nullptr, *sy = nullptr;
    int nFeat = 0, nEval = 0, nEvec = 0, nSq = 0;
    for (int i = 0; i < n_in; i++) {
        const float* p = (const float*)d_in[i];
        int n = in_sizes[i];
        if (n == VDIM * MDIM)      { if (nFeat++ == 0) fx = p; else fy = p; }
        else if (n == KDIM)        { if (nEval++ == 0) ex = p; else ey = p; }
        else if (n == KDIM * VDIM) { if (nEvec++ == 0) tx = p; else ty = p; }
        else if (n == KDIM * KDIM) { if (nSq++   == 0) sx = p; else sy = p; }
    }

    dim3 gB(NCH, 4, 2);
    big_gemm<<<gB, 256>>>(fx, fy, tx, ty);
    reduce_AT<<<132, 256>>>(sy);
    setup1<<<8, 256>>>();
    setup2<<<7, 256>>>(sx);
    setup3<<<16, 256>>>(ex, ey);
    setup4<<<20, 256>>>(ey);
    setup5<<<4, 256>>>();
    for (int it = 0; it < NITER; ++it) {
        iterA<<<12, 256>>>();
        iterB<<<4, 256>>>(ey, (it == NITER - 1) ? (float*)d_out : nullptr);
    }
}